// round 1
// baseline (speedup 1.0000x reference)
#include <cuda_runtime.h>
#include <cstdint>
#include <math.h>

// NetSimile on 8 block-diagonal graphs of 512 nodes, dense A[4096,4096] in {0,1}.
// Exploits: block-diagonality (only read 8 diagonal 512x512 blocks), binary
// adjacency (bitset rows, B = M1@A via popcount of AND), tiny per-graph stats.

#define NN 4096
#define GG 8
#define MM 512
#define WW 16   // 512 bits = 16 u32 words per row

__device__ uint32_t g_bits[NN][WW];   // adjacency bitsets (no self bit; diag of A is 0)
__device__ int      g_deg[NN];
__device__ float    g_feat[7][NN];

// ---------------------------------------------------------------------------
// K1: build per-row bitsets of the diagonal block + degree. One warp per row.
// ---------------------------------------------------------------------------
__global__ void k_bits(const float* __restrict__ A) {
    int warp = (blockIdx.x * blockDim.x + threadIdx.x) >> 5;
    int lane = threadIdx.x & 31;
    if (warp >= NN) return;
    int g = warp / MM;
    const float* row = A + (size_t)warp * NN + (size_t)g * MM;
    uint32_t myword = 0;
    int deg = 0;
#pragma unroll
    for (int w = 0; w < WW; w++) {
        float v = row[w * 32 + lane];
        unsigned m = __ballot_sync(0xffffffffu, v != 0.0f);
        deg += __popc(m);
        if (lane == w) myword = m;
    }
    if (lane < WW) g_bits[warp][lane] = myword;
    if (lane == 0) g_deg[warp] = deg;
}

// ---------------------------------------------------------------------------
// K2: per-node features f0,f1,f2,f4,f5,f6. One warp per node, 8 warps/block,
// block's graph bitsets staged in shared (padded to 17 words -> conflict-free).
// ---------------------------------------------------------------------------
__global__ void k_feat() {
    __shared__ uint32_t sbits[MM][WW + 1];
    __shared__ int sdeg[MM];
    int tid = threadIdx.x;
    int node0 = blockIdx.x * 8;          // 8 nodes per block, all in same graph
    int g = node0 / MM;
    int base = g * MM;

    for (int idx = tid; idx < MM * WW; idx += 256) {
        int v = idx >> 4, w = idx & 15;
        sbits[v][w] = g_bits[base + v][w];
    }
    for (int idx = tid; idx < MM; idx += 256) sdeg[idx] = g_deg[base + idx];
    __syncthreads();

    int warpId = tid >> 5, lane = tid & 31;
    int n = node0 + warpId;
    int r = n - base;

    uint32_t m1[WW];
#pragma unroll
    for (int w = 0; w < WW; w++) m1[w] = sbits[r][w];
    m1[r >> 5] |= 1u << (r & 31);        // M1 = A | I (self bit)

    int f4 = 0, sumdeg2 = 0, cnt2 = 0, sumdegn = 0;
    for (int v = lane; v < MM; v += 32) {
        int b = 0;
#pragma unroll
        for (int w = 0; w < WW; w++) b += __popc(m1[w] & sbits[v][w]);
        bool m1b = (m1[v >> 5] >> (v & 31)) & 1u;
        bool m2b = m1b || (b > 0);       // M2 = M1 | (B > 0)
        if (m1b) f4 += b;                // (B * M1) row sum
        if (m2b) { cnt2++; sumdeg2 += sdeg[v]; }
        if (m1b && v != r) sumdegn += sdeg[v];   // neighbors only (A bit)
    }
    f4      = __reduce_add_sync(0xffffffffu, f4);
    sumdeg2 = __reduce_add_sync(0xffffffffu, sumdeg2);
    cnt2    = __reduce_add_sync(0xffffffffu, cnt2);
    sumdegn = __reduce_add_sync(0xffffffffu, sumdegn);

    if (lane == 0) {
        float deg = (float)sdeg[r];
        float f0 = deg;
        float f2 = (deg > 0.f) ? (float)sumdegn / deg : 0.f;
        float f1 = (deg > 1.f) ? 2.0f * ((float)f4 - deg) / (deg * (deg - 1.0f)) : 0.f;
        float f4o = 0.5f * (float)f4;
        float f5 = (float)sumdeg2 - 2.0f * (float)f4;
        float f6 = (float)cnt2 - deg - 1.0f;
        g_feat[0][n] = f0;
        g_feat[1][n] = f1;
        g_feat[2][n] = f2;
        g_feat[4][n] = f4o;
        g_feat[5][n] = f5;
        g_feat[6][n] = f6;
    }
}

// ---------------------------------------------------------------------------
// K3: f3 = scatter_mean of neighbor f1. One warp per node; word k is a
// broadcast load, bit 'lane' selects neighbor (k*32+lane).
// ---------------------------------------------------------------------------
__global__ void k_f3() {
    int warp = (blockIdx.x * blockDim.x + threadIdx.x) >> 5;
    int lane = threadIdx.x & 31;
    if (warp >= NN) return;
    int g = warp / MM;
    int base = g * MM;
    float s = 0.f;
#pragma unroll
    for (int k = 0; k < WW; k++) {
        uint32_t w = g_bits[warp][k];
        if ((w >> lane) & 1u) s += g_feat[1][base + k * 32 + lane];
    }
#pragma unroll
    for (int o = 16; o; o >>= 1) s += __shfl_xor_sync(0xffffffffu, s, o);
    if (lane == 0) {
        float deg = (float)g_deg[warp];
        g_feat[3][warp] = (deg > 0.f) ? s / deg : 0.f;
    }
}

// ---------------------------------------------------------------------------
// K4: per (graph, feature) stats. 56 blocks x 256 threads over 512 values.
// mean/m2/m3/m4 in fp64; lower-median via exact rank counting.
// ---------------------------------------------------------------------------
__global__ void k_stats(float* __restrict__ out) {
    __shared__ float x[MM];
    __shared__ double red[4][8];
    __shared__ float medv;
    __shared__ double smean, sm2, sm3, sm4;

    int f = blockIdx.x % 7, g = blockIdx.x / 7;
    int tid = threadIdx.x;
    for (int i = tid; i < MM; i += 256) x[i] = g_feat[f][g * MM + i];
    __syncthreads();

    // pass 1: mean
    double s = (double)x[tid] + (double)x[tid + 256];
#pragma unroll
    for (int o = 16; o; o >>= 1) s += __shfl_xor_sync(0xffffffffu, s, o);
    if ((tid & 31) == 0) red[0][tid >> 5] = s;
    __syncthreads();
    if (tid == 0) {
        double t = 0;
        for (int i = 0; i < 8; i++) t += red[0][i];
        smean = t / (double)MM;
    }
    __syncthreads();
    double mean = smean;

    // pass 2: central moments 2,3,4
    double c0 = (double)x[tid] - mean, c1 = (double)x[tid + 256] - mean;
    double p0 = c0 * c0, p1 = c1 * c1;
    double s2 = p0 + p1;
    double s3 = p0 * c0 + p1 * c1;
    double s4 = p0 * p0 + p1 * p1;
#pragma unroll
    for (int o = 16; o; o >>= 1) {
        s2 += __shfl_xor_sync(0xffffffffu, s2, o);
        s3 += __shfl_xor_sync(0xffffffffu, s3, o);
        s4 += __shfl_xor_sync(0xffffffffu, s4, o);
    }
    if ((tid & 31) == 0) {
        red[1][tid >> 5] = s2;
        red[2][tid >> 5] = s3;
        red[3][tid >> 5] = s4;
    }
    __syncthreads();
    if (tid == 0) {
        double t2 = 0, t3 = 0, t4 = 0;
        for (int i = 0; i < 8; i++) { t2 += red[1][i]; t3 += red[2][i]; t4 += red[3][i]; }
        sm2 = t2 / (double)MM; sm3 = t3 / (double)MM; sm4 = t4 / (double)MM;
    }

    // median: element at sorted index (MM-1)/2 = 255 (lower middle), stable rank
    for (int ii = tid; ii < MM; ii += 256) {
        float xi = x[ii];
        int rank = 0;
        for (int j = 0; j < MM; j++) {
            float xj = x[j];
            rank += (xj < xi) || (xj == xi && j < ii);
        }
        if (rank == (MM - 1) / 2) medv = xi;
    }
    __syncthreads();

    if (tid == 0) {
        double m2 = sm2, m3 = sm3, m4 = sm4;
        double eps = 1e-4;
        out[g * 35 + 0  + f] = (float)smean;
        out[g * 35 + 7  + f] = medv;
        out[g * 35 + 14 + f] = (float)sqrt(m2);
        out[g * 35 + 21 + f] = (float)(m3 / fmax(pow(m2, 1.5), eps));
        out[g * 35 + 28 + f] = (float)(m4 / fmax(m2 * m2, eps));
    }
}

extern "C" void kernel_launch(void* const* d_in, const int* in_sizes, int n_in,
                              void* d_out, int out_size) {
    const float* A = (const float*)d_in[0];
    float* out = (float*)d_out;

    k_bits<<<NN / 8, 256>>>(A);          // 4096 warps
    k_feat<<<NN / 8, 256>>>();           // 8 warps/block, 8 nodes/block
    k_f3<<<NN / 8, 256>>>();
    k_stats<<<GG * 7, 256>>>(out);
}